// round 1
// baseline (speedup 1.0000x reference)
#include <cuda_runtime.h>

// ---------------------------------------------------------------------------
// Problem constants
// ---------------------------------------------------------------------------
constexpr int Bsz = 8;
constexpr int S   = 768;
constexpr int Hd  = 768;
constexpr int NH  = 12;
constexpr int HDm = 64;
constexpr int NL  = 5;
constexpr int BS  = Bsz * S;          // 6144 rows

// ---------------------------------------------------------------------------
// Scratch (static device globals; no runtime allocation allowed)
// ---------------------------------------------------------------------------
__device__ float g_q  [BS * Hd];
__device__ float g_k  [BS * Hd];
__device__ float g_Q  [BS * Hd];
__device__ float g_K  [BS * Hd];
__device__ float g_V  [BS * Hd];
__device__ float g_ctx[BS * Hd];
__device__ float g_al [BS * Hd];
__device__ float g_al2[BS * Hd];
__device__ float g_o  [BS * Hd];

__device__ float g_F [NL * 8 * Hd * Hd];   // chain leaf factors
__device__ float g_P1[NL * 4 * Hd * Hd];   // tree level 1
__device__ float g_P2[NL * 2 * Hd * Hd];   // tree level 2
__device__ float g_M [NL     * Hd * Hd];   // final per-language M

__device__ unsigned char g_fF [NL * 8];
__device__ unsigned char g_fP1[NL * 4];
__device__ unsigned char g_fP2[NL * 2];

// ---------------------------------------------------------------------------
// SGEMM (NT): C[r, o] = sum_i A[r, i] * W[o, i] + bias[o]
// A: [R x 768], W: [768 x 768] (row o), C: [R x 768]
// 128x128 tile, BK=8, 256 threads, 8x8 per thread.
// WSEL=1: per-batch language-selected W/bias (grid.z = batch).
// ---------------------------------------------------------------------------
template <int WSEL>
__global__ __launch_bounds__(256) void sgemm_nt(
    const float* __restrict__ A, long long sA,
    const float* __restrict__ W, const float* __restrict__ bias,
    const int* __restrict__ lang,
    float* __restrict__ C, long long sC)
{
    const int z = blockIdx.z;
    A += (long long)z * sA;
    C += (long long)z * sC;
    if (WSEL) {
        const int lg = __ldg(&lang[z]);
        W    += (long long)lg * Hd * Hd;
        bias += lg * Hd;
    }

    __shared__ float As[8][132];
    __shared__ float Ws[8][132];

    const int tid = threadIdx.x;
    const int m0 = blockIdx.y * 128;
    const int n0 = blockIdx.x * 128;
    const int lr = tid >> 1;
    const int lk = (tid & 1) * 4;
    const float* Ap = A + (long long)(m0 + lr) * Hd + lk;
    const float* Wp = W + (long long)(n0 + lr) * Hd + lk;
    const int ty = tid >> 4, tx = tid & 15;

    float acc[8][8];
#pragma unroll
    for (int i = 0; i < 8; i++)
#pragma unroll
        for (int j = 0; j < 8; j++) acc[i][j] = 0.f;

    float4 av = *(const float4*)Ap;
    float4 wv = *(const float4*)Wp;

    for (int k0 = 0; k0 < Hd; k0 += 8) {
        __syncthreads();
        As[lk + 0][lr] = av.x; As[lk + 1][lr] = av.y;
        As[lk + 2][lr] = av.z; As[lk + 3][lr] = av.w;
        Ws[lk + 0][lr] = wv.x; Ws[lk + 1][lr] = wv.y;
        Ws[lk + 2][lr] = wv.z; Ws[lk + 3][lr] = wv.w;
        __syncthreads();
        if (k0 + 8 < Hd) {
            av = *(const float4*)(Ap + k0 + 8);
            wv = *(const float4*)(Wp + k0 + 8);
        }
#pragma unroll
        for (int k = 0; k < 8; k++) {
            float a[8], b[8];
            *(float4*)&a[0] = *(const float4*)&As[k][ty * 8];
            *(float4*)&a[4] = *(const float4*)&As[k][ty * 8 + 4];
            *(float4*)&b[0] = *(const float4*)&Ws[k][tx * 8];
            *(float4*)&b[4] = *(const float4*)&Ws[k][tx * 8 + 4];
#pragma unroll
            for (int i = 0; i < 8; i++)
#pragma unroll
                for (int j = 0; j < 8; j++) acc[i][j] += a[i] * b[j];
        }
    }

    float bn[8];
#pragma unroll
    for (int j = 0; j < 8; j++) bn[j] = __ldg(&bias[n0 + tx * 8 + j]);
#pragma unroll
    for (int i = 0; i < 8; i++) {
        float* cp = C + (long long)(m0 + ty * 8 + i) * Hd + n0 + tx * 8;
        float4 v0 = make_float4(acc[i][0] + bn[0], acc[i][1] + bn[1],
                                acc[i][2] + bn[2], acc[i][3] + bn[3]);
        float4 v1 = make_float4(acc[i][4] + bn[4], acc[i][5] + bn[5],
                                acc[i][6] + bn[6], acc[i][7] + bn[7]);
        *(float4*)cp       = v0;
        *(float4*)(cp + 4) = v1;
    }
}

// ---------------------------------------------------------------------------
// Shared NN GEMM tile core: C = A(768-K) @ W(768x768), no bias.
// ---------------------------------------------------------------------------
__device__ __forceinline__ void nn_gemm_tile(
    const float* __restrict__ A, const float* __restrict__ W,
    float* __restrict__ C)
{
    __shared__ float As[8][132];
    __shared__ float Ws[8][132];

    const int tid = threadIdx.x;
    const int m0 = blockIdx.y * 128;
    const int n0 = blockIdx.x * 128;
    const int lrA = tid >> 1;
    const int lkA = (tid & 1) * 4;
    const int krW = tid >> 5;
    const int ncW = (tid & 31) * 4;
    const float* Ap = A + (long long)(m0 + lrA) * Hd + lkA;
    const float* Wp = W + (long long)krW * Hd + n0 + ncW;
    const int ty = tid >> 4, tx = tid & 15;

    float acc[8][8];
#pragma unroll
    for (int i = 0; i < 8; i++)
#pragma unroll
        for (int j = 0; j < 8; j++) acc[i][j] = 0.f;

    float4 av = *(const float4*)Ap;
    float4 wv = *(const float4*)Wp;

    for (int k0 = 0; k0 < Hd; k0 += 8) {
        __syncthreads();
        As[lkA + 0][lrA] = av.x; As[lkA + 1][lrA] = av.y;
        As[lkA + 2][lrA] = av.z; As[lkA + 3][lrA] = av.w;
        *(float4*)&Ws[krW][ncW] = wv;
        __syncthreads();
        if (k0 + 8 < Hd) {
            av = *(const float4*)(Ap + k0 + 8);
            wv = *(const float4*)(Wp + (long long)(k0 + 8) * Hd);
        }
#pragma unroll
        for (int k = 0; k < 8; k++) {
            float a[8], b[8];
            *(float4*)&a[0] = *(const float4*)&As[k][ty * 8];
            *(float4*)&a[4] = *(const float4*)&As[k][ty * 8 + 4];
            *(float4*)&b[0] = *(const float4*)&Ws[k][tx * 8];
            *(float4*)&b[4] = *(const float4*)&Ws[k][tx * 8 + 4];
#pragma unroll
            for (int i = 0; i < 8; i++)
#pragma unroll
                for (int j = 0; j < 8; j++) acc[i][j] += a[i] * b[j];
        }
    }

#pragma unroll
    for (int i = 0; i < 8; i++) {
        float* cp = C + (long long)(m0 + ty * 8 + i) * Hd + n0 + tx * 8;
        float4 v0 = make_float4(acc[i][0], acc[i][1], acc[i][2], acc[i][3]);
        float4 v1 = make_float4(acc[i][4], acc[i][5], acc[i][6], acc[i][7]);
        *(float4*)cp       = v0;
        *(float4*)(cp + 4) = v1;
    }
}

// ---------------------------------------------------------------------------
// Chain-factor / tree kernels
// ---------------------------------------------------------------------------
__global__ void k_flags(const int* __restrict__ lang,
                        unsigned char* fF, unsigned char* fP1, unsigned char* fP2)
{
    if (threadIdx.x == 0 && blockIdx.x == 0) {
        for (int a = 0; a < NL; a++) {
            for (int j = 0; j < 8; j++) fF[a * 8 + j] = (lang[j] == a) ? 1 : 0;
            for (int p = 0; p < 4; p++)
                fP1[a * 4 + p] = fF[a * 8 + 2 * p] & fF[a * 8 + 2 * p + 1];
            for (int p = 0; p < 2; p++)
                fP2[a * 2 + p] = fP1[a * 4 + 2 * p] & fP1[a * 4 + 2 * p + 1];
        }
    }
}

// F[a][j] = (lang[j]==a) ? I : align[a, lang[j]]   (grid: (Hd*Hd/1024, NL*8))
__global__ __launch_bounds__(256) void k_factors(
    const float* __restrict__ alignT, const int* __restrict__ lang,
    float* __restrict__ F)
{
    const int node = blockIdx.y;
    const int a = node >> 3, j = node & 7;
    const int c = __ldg(&lang[j]);
    float* dst = F + (long long)node * Hd * Hd;
    const int idx4 = (blockIdx.x * 256 + threadIdx.x) * 4;
    if (c == a) {
        const int r = idx4 / Hd, col = idx4 % Hd;
        float4 v;
        v.x = (col + 0 == r) ? 1.f : 0.f;
        v.y = (col + 1 == r) ? 1.f : 0.f;
        v.z = (col + 2 == r) ? 1.f : 0.f;
        v.w = (col + 3 == r) ? 1.f : 0.f;
        *(float4*)(dst + idx4) = v;
    } else {
        const float* sm = alignT + (long long)(a * NL + c) * Hd * Hd;
        *(float4*)(dst + idx4) = *(const float4*)(sm + idx4);
    }
}

// One tree level: dst[z] = src[2p] @ src[2p+1] with identity shortcuts.
__global__ __launch_bounds__(256) void k_chain(
    const float* __restrict__ src, const unsigned char* __restrict__ fs,
    float* __restrict__ dst, int spa, int dpa)
{
    const int z = blockIdx.z;
    const int a = z / dpa, p = z - a * dpa;
    const int li = a * spa + 2 * p;
    const float* L = src + (long long)li * Hd * Hd;
    const float* R = L + (long long)Hd * Hd;
    float* C = dst + (long long)z * Hd * Hd;
    const unsigned char f1 = fs[li], f2 = fs[li + 1];

    const int tid = threadIdx.x;
    const int m0 = blockIdx.y * 128;
    const int n0 = blockIdx.x * 128;

    if (f1 & f2) {                       // both identity -> write I
#pragma unroll
        for (int u = 0; u < 16; u++) {
            const int fidx = u * 256 + tid;
            const int r = fidx >> 5;
            const int c = (fidx & 31) * 4;
            const int gr = m0 + r, gc = n0 + c;
            float4 v;
            v.x = (gc + 0 == gr) ? 1.f : 0.f;
            v.y = (gc + 1 == gr) ? 1.f : 0.f;
            v.z = (gc + 2 == gr) ? 1.f : 0.f;
            v.w = (gc + 3 == gr) ? 1.f : 0.f;
            *(float4*)(C + (long long)gr * Hd + gc) = v;
        }
        return;
    }
    if (f1 | f2) {                       // one identity -> copy the other
        const float* Smat = f1 ? R : L;
#pragma unroll
        for (int u = 0; u < 16; u++) {
            const int fidx = u * 256 + tid;
            const int r = fidx >> 5;
            const int c = (fidx & 31) * 4;
            *(float4*)(C + (long long)(m0 + r) * Hd + n0 + c) =
                *(const float4*)(Smat + (long long)(m0 + r) * Hd + n0 + c);
        }
        return;
    }
    nn_gemm_tile(L, R, C);
}

// aligned[b] @ M[lang[b]]
__global__ __launch_bounds__(256) void k_alignM(
    const float* __restrict__ A, const float* __restrict__ M,
    const int* __restrict__ lang, float* __restrict__ C)
{
    const int z = blockIdx.z;
    const int lg = __ldg(&lang[z]);
    nn_gemm_tile(A + (long long)z * S * Hd,
                 M + (long long)lg * Hd * Hd,
                 C + (long long)z * S * Hd);
}

// ---------------------------------------------------------------------------
// Flash attention: grid (S/64, NH, B), 256 threads.
// Q pre-scaled by 0.125 (1/sqrt(64)). K stored transposed; P aliases K buffer.
// ---------------------------------------------------------------------------
__global__ __launch_bounds__(256) void k_attn(
    const float* __restrict__ Q, const float* __restrict__ K,
    const float* __restrict__ V, float* __restrict__ O)
{
    __shared__ float Qs[64 * 64];
    __shared__ float KP[64 * 64];   // K (transposed [d][k]) then P ([q][k])
    __shared__ float Vs[64 * 64];

    const int qt = blockIdx.x, h = blockIdx.y, b = blockIdx.z;
    const int tid = threadIdx.x;
    const int ty = tid >> 4, tx = tid & 15;
    const long long qbase = ((long long)(b * S + qt * 64)) * Hd + h * 64;

#pragma unroll
    for (int u = 0; u < 4; u++) {
        const int fidx = u * 256 + tid;
        const int r = fidx >> 4;
        const int d = (fidx & 15) * 4;
        float4 v = *(const float4*)(Q + qbase + (long long)r * Hd + d);
        v.x *= 0.125f; v.y *= 0.125f; v.z *= 0.125f; v.w *= 0.125f;
        *(float4*)&Qs[r * 64 + d] = v;
    }

    float m[4], l[4], o[4][4];
#pragma unroll
    for (int i = 0; i < 4; i++) {
        m[i] = -1e30f; l[i] = 0.f;
#pragma unroll
        for (int j = 0; j < 4; j++) o[i][j] = 0.f;
    }

    for (int kt = 0; kt < S / 64; kt++) {
        const long long kbase = ((long long)(b * S + kt * 64)) * Hd + h * 64;
        __syncthreads();
#pragma unroll
        for (int u = 0; u < 4; u++) {
            const int fidx = u * 256 + tid;
            const int r = fidx >> 4;
            const int d = (fidx & 15) * 4;
            float4 kv = *(const float4*)(K + kbase + (long long)r * Hd + d);
            KP[(d + 0) * 64 + r] = kv.x;
            KP[(d + 1) * 64 + r] = kv.y;
            KP[(d + 2) * 64 + r] = kv.z;
            KP[(d + 3) * 64 + r] = kv.w;
            *(float4*)&Vs[r * 64 + d] =
                *(const float4*)(V + kbase + (long long)r * Hd + d);
        }
        __syncthreads();

        float s[4][4];
#pragma unroll
        for (int i = 0; i < 4; i++)
#pragma unroll
            for (int j = 0; j < 4; j++) s[i][j] = 0.f;

#pragma unroll
        for (int d0 = 0; d0 < 64; d0 += 4) {
            float a0[4], a1[4], a2[4], a3[4];
            *(float4*)a0 = *(const float4*)&Qs[(ty * 4 + 0) * 64 + d0];
            *(float4*)a1 = *(const float4*)&Qs[(ty * 4 + 1) * 64 + d0];
            *(float4*)a2 = *(const float4*)&Qs[(ty * 4 + 2) * 64 + d0];
            *(float4*)a3 = *(const float4*)&Qs[(ty * 4 + 3) * 64 + d0];
#pragma unroll
            for (int dd = 0; dd < 4; dd++) {
                const float b0 = KP[(d0 + dd) * 64 + tx];
                const float b1 = KP[(d0 + dd) * 64 + tx + 16];
                const float b2 = KP[(d0 + dd) * 64 + tx + 32];
                const float b3 = KP[(d0 + dd) * 64 + tx + 48];
                s[0][0] += a0[dd] * b0; s[0][1] += a0[dd] * b1;
                s[0][2] += a0[dd] * b2; s[0][3] += a0[dd] * b3;
                s[1][0] += a1[dd] * b0; s[1][1] += a1[dd] * b1;
                s[1][2] += a1[dd] * b2; s[1][3] += a1[dd] * b3;
                s[2][0] += a2[dd] * b0; s[2][1] += a2[dd] * b1;
                s[2][2] += a2[dd] * b2; s[2][3] += a2[dd] * b3;
                s[3][0] += a3[dd] * b0; s[3][1] += a3[dd] * b1;
                s[3][2] += a3[dd] * b2; s[3][3] += a3[dd] * b3;
            }
        }

        float p[4][4];
#pragma unroll
        for (int i = 0; i < 4; i++) {
            float mx = fmaxf(fmaxf(s[i][0], s[i][1]), fmaxf(s[i][2], s[i][3]));
#pragma unroll
            for (int off = 8; off >= 1; off >>= 1)
                mx = fmaxf(mx, __shfl_xor_sync(0xffffffffu, mx, off));
            const float mn = fmaxf(m[i], mx);
            const float alpha = __expf(m[i] - mn);
            m[i] = mn;
            float rs = 0.f;
#pragma unroll
            for (int j = 0; j < 4; j++) {
                p[i][j] = __expf(s[i][j] - mn);
                rs += p[i][j];
            }
#pragma unroll
            for (int off = 8; off >= 1; off >>= 1)
                rs += __shfl_xor_sync(0xffffffffu, rs, off);
            l[i] = l[i] * alpha + rs;
            o[i][0] *= alpha; o[i][1] *= alpha;
            o[i][2] *= alpha; o[i][3] *= alpha;
        }

        __syncthreads();
#pragma unroll
        for (int i = 0; i < 4; i++)
#pragma unroll
            for (int j = 0; j < 4; j++)
                KP[(ty * 4 + i) * 64 + tx + 16 * j] = p[i][j];
        __syncthreads();

#pragma unroll
        for (int k = 0; k < 64; k++) {
            const float4 v = *(const float4*)&Vs[k * 64 + tx * 4];
            const float p0 = KP[(ty * 4 + 0) * 64 + k];
            const float p1 = KP[(ty * 4 + 1) * 64 + k];
            const float p2 = KP[(ty * 4 + 2) * 64 + k];
            const float p3 = KP[(ty * 4 + 3) * 64 + k];
            o[0][0] += p0 * v.x; o[0][1] += p0 * v.y; o[0][2] += p0 * v.z; o[0][3] += p0 * v.w;
            o[1][0] += p1 * v.x; o[1][1] += p1 * v.y; o[1][2] += p1 * v.z; o[1][3] += p1 * v.w;
            o[2][0] += p2 * v.x; o[2][1] += p2 * v.y; o[2][2] += p2 * v.z; o[2][3] += p2 * v.w;
            o[3][0] += p3 * v.x; o[3][1] += p3 * v.y; o[3][2] += p3 * v.z; o[3][3] += p3 * v.w;
        }
    }

#pragma unroll
    for (int i = 0; i < 4; i++) {
        const float inv = 1.f / l[i];
        float4 v = make_float4(o[i][0] * inv, o[i][1] * inv,
                               o[i][2] * inv, o[i][3] * inv);
        *(float4*)(O + qbase + (long long)(ty * 4 + i) * Hd + tx * 4) = v;
    }
}

// ---------------------------------------------------------------------------
// Residual + LayerNorm: one block per row.
// ---------------------------------------------------------------------------
__global__ __launch_bounds__(256) void k_ln(
    const float* __restrict__ X, const float* __restrict__ Rres,
    const float* __restrict__ gam, const float* __restrict__ bet,
    float* __restrict__ out)
{
    const int row = blockIdx.x;
    const long long base = (long long)row * Hd;
    const int tid = threadIdx.x;

    float v[3];
    float s = 0.f, s2 = 0.f;
#pragma unroll
    for (int u = 0; u < 3; u++) {
        const int idx = tid + u * 256;
        const float val = X[base + idx] + Rres[base + idx];
        v[u] = val; s += val; s2 += val * val;
    }
#pragma unroll
    for (int off = 16; off >= 1; off >>= 1) {
        s  += __shfl_xor_sync(0xffffffffu, s, off);
        s2 += __shfl_xor_sync(0xffffffffu, s2, off);
    }
    __shared__ float ss[8], ss2[8], mv[2];
    const int wid = tid >> 5, lane = tid & 31;
    if (lane == 0) { ss[wid] = s; ss2[wid] = s2; }
    __syncthreads();
    if (tid == 0) {
        float S_ = 0.f, S2_ = 0.f;
        for (int w = 0; w < 8; w++) { S_ += ss[w]; S2_ += ss2[w]; }
        const float mean = S_ * (1.f / 768.f);
        const float var  = S2_ * (1.f / 768.f) - mean * mean;
        mv[0] = mean;
        mv[1] = rsqrtf(var + 1e-5f);
    }
    __syncthreads();
    const float mean = mv[0], rstd = mv[1];
#pragma unroll
    for (int u = 0; u < 3; u++) {
        const int idx = tid + u * 256;
        out[base + idx] = (v[u] - mean) * rstd * gam[idx] + bet[idx];
    }
}

// ---------------------------------------------------------------------------
// kernel_launch
// ---------------------------------------------------------------------------
extern "C" void kernel_launch(void* const* d_in, const int* in_sizes, int n_in,
                              void* d_out, int out_size)
{
    const float* hs      = (const float*)d_in[0];
    const int*   lang    = (const int*)  d_in[1];
    // d_in[2] attention_mask: unused (all ones, reference ignores it)
    const float* Wq_lang = (const float*)d_in[3];
    const float* bq_lang = (const float*)d_in[4];
    const float* Wk_lang = (const float*)d_in[5];
    const float* bk_lang = (const float*)d_in[6];
    const float* in_w    = (const float*)d_in[7];
    const float* in_b    = (const float*)d_in[8];
    const float* out_w   = (const float*)d_in[9];
    const float* out_b   = (const float*)d_in[10];
    const float* alignT  = (const float*)d_in[11];
    const float* proj_w  = (const float*)d_in[12];
    const float* proj_b  = (const float*)d_in[13];
    const float* ln_g    = (const float*)d_in[14];
    const float* ln_b    = (const float*)d_in[15];
    float* out = (float*)d_out;

    float *q, *k, *Qp, *Kp, *Vp, *ctx, *al, *al2, *obuf;
    float *F, *P1, *P2, *M;
    unsigned char *fF, *fP1, *fP2;
    cudaGetSymbolAddress((void**)&q,    g_q);
    cudaGetSymbolAddress((void**)&k,    g_k);
    cudaGetSymbolAddress((void**)&Qp,   g_Q);
    cudaGetSymbolAddress((void**)&Kp,   g_K);
    cudaGetSymbolAddress((void**)&Vp,   g_V);
    cudaGetSymbolAddress((void**)&ctx,  g_ctx);
    cudaGetSymbolAddress((void**)&al,   g_al);
    cudaGetSymbolAddress((void**)&al2,  g_al2);
    cudaGetSymbolAddress((void**)&obuf, g_o);
    cudaGetSymbolAddress((void**)&F,    g_F);
    cudaGetSymbolAddress((void**)&P1,   g_P1);
    cudaGetSymbolAddress((void**)&P2,   g_P2);
    cudaGetSymbolAddress((void**)&M,    g_M);
    cudaGetSymbolAddress((void**)&fF,   g_fF);
    cudaGetSymbolAddress((void**)&fP1,  g_fP1);
    cudaGetSymbolAddress((void**)&fP2,  g_fP2);

    const long long sBH = (long long)S * Hd;
    const dim3 thr(256);

    // --- M-chain (independent of main path; launched first) ---
    k_flags<<<1, 32>>>(lang, fF, fP1, fP2);
    k_factors<<<dim3(Hd * Hd / 1024, NL * 8), thr>>>(alignT, lang, F);
    k_chain<<<dim3(6, 6, NL * 4), thr>>>(F,  fF,  P1, 8, 4);
    k_chain<<<dim3(6, 6, NL * 2), thr>>>(P1, fP1, P2, 4, 2);
    k_chain<<<dim3(6, 6, NL    ), thr>>>(P2, fP2, M,  2, 1);

    // --- per-language q/k projections ---
    sgemm_nt<1><<<dim3(6, 6, Bsz), thr>>>(hs, sBH, Wq_lang, bq_lang, lang, q, sBH);
    sgemm_nt<1><<<dim3(6, 6, Bsz), thr>>>(hs, sBH, Wk_lang, bk_lang, lang, k, sBH);

    // --- QKV ---
    sgemm_nt<0><<<dim3(6, 48, 1), thr>>>(q,  0, in_w,                in_b,          nullptr, Qp, 0);
    sgemm_nt<0><<<dim3(6, 48, 1), thr>>>(k,  0, in_w + Hd * Hd,      in_b + Hd,     nullptr, Kp, 0);
    sgemm_nt<0><<<dim3(6, 48, 1), thr>>>(hs, 0, in_w + 2 * Hd * Hd,  in_b + 2 * Hd, nullptr, Vp, 0);

    // --- attention ---
    k_attn<<<dim3(S / 64, NH, Bsz), thr>>>(Qp, Kp, Vp, ctx);

    // --- out_proj ---
    sgemm_nt<0><<<dim3(6, 48, 1), thr>>>(ctx, 0, out_w, out_b, nullptr, al, 0);

    // --- aligned @ M[lang[b]] ---
    k_alignM<<<dim3(6, 6, Bsz), thr>>>(al, M, lang, al2);

    // --- final proj ---
    sgemm_nt<0><<<dim3(6, 48, 1), thr>>>(al2, 0, proj_w, proj_b, nullptr, obuf, 0);

    // --- residual + LayerNorm ---
    k_ln<<<BS, thr>>>(obuf, hs, ln_g, ln_b, out);
}

// round 3
// speedup vs baseline: 1.6084x; 1.6084x over previous
#include <cuda_runtime.h>
#include <cuda_bf16.h>
#include <cstdint>

// ---------------------------------------------------------------------------
// Problem constants
// ---------------------------------------------------------------------------
constexpr int Bsz = 8;
constexpr int S   = 768;
constexpr int Hd  = 768;
constexpr int NH  = 12;
constexpr int NL  = 5;
constexpr int BS  = Bsz * S;                 // 6144 rows
constexpr long long HH = (long long)Hd * Hd; // 589824

typedef __nv_bfloat16 bf16;

// ---------------------------------------------------------------------------
// Scratch (static device globals)
// ---------------------------------------------------------------------------
// fp32 activations
__device__ float g_Q  [BS * Hd];
__device__ float g_K  [BS * Hd];
__device__ float g_V  [BS * Hd];
__device__ float g_ctx[BS * Hd];
__device__ float g_o  [BS * Hd];

// bf16 hi/lo activations
__device__ bf16 g_hs_h [BS * Hd], g_hs_l [BS * Hd];
__device__ bf16 g_q_h  [BS * Hd], g_q_l  [BS * Hd];
__device__ bf16 g_k_h  [BS * Hd], g_k_l  [BS * Hd];
__device__ bf16 g_ctx_h[BS * Hd], g_ctx_l[BS * Hd];
__device__ bf16 g_al_h [BS * Hd], g_al_l [BS * Hd];
__device__ bf16 g_al2_h[BS * Hd], g_al2_l[BS * Hd];

// bf16 hi/lo weights
__device__ bf16 g_Wq_h [NL * Hd * Hd], g_Wq_l [NL * Hd * Hd];
__device__ bf16 g_Wk_h [NL * Hd * Hd], g_Wk_l [NL * Hd * Hd];
__device__ bf16 g_inw_h[3 * Hd * Hd],  g_inw_l[3 * Hd * Hd];
__device__ bf16 g_ow_h [Hd * Hd],      g_ow_l [Hd * Hd];
__device__ bf16 g_pw_h [Hd * Hd],      g_pw_l [Hd * Hd];

// chain nodes: normal + transposed, hi + lo
__device__ bf16 g_F_h [NL * 8 * Hd * Hd], g_F_l [NL * 8 * Hd * Hd];
__device__ bf16 g_FT_h[NL * 8 * Hd * Hd], g_FT_l[NL * 8 * Hd * Hd];
__device__ bf16 g_P1_h[NL * 4 * Hd * Hd], g_P1_l[NL * 4 * Hd * Hd];
__device__ bf16 g_QT1_h[NL * 4 * Hd * Hd], g_QT1_l[NL * 4 * Hd * Hd];
__device__ bf16 g_P2_h[NL * 2 * Hd * Hd], g_P2_l[NL * 2 * Hd * Hd];
__device__ bf16 g_QT2_h[NL * 2 * Hd * Hd], g_QT2_l[NL * 2 * Hd * Hd];
__device__ bf16 g_M_h [NL * Hd * Hd],     g_M_l [NL * Hd * Hd];
__device__ bf16 g_MT_h[NL * Hd * Hd],     g_MT_l[NL * Hd * Hd];

__device__ unsigned char g_fF [NL * 8];
__device__ unsigned char g_fP1[NL * 4];
__device__ unsigned char g_fP2[NL * 2];

// ---------------------------------------------------------------------------
// Small PTX helpers
// ---------------------------------------------------------------------------
__device__ __forceinline__ uint32_t smem_u32(const void* p) {
    return (uint32_t)__cvta_generic_to_shared(p);
}

__device__ __forceinline__ void cp16(uint32_t d, const void* s) {
    asm volatile("cp.async.cg.shared.global [%0], [%1], 16;"
                 :: "r"(d), "l"(s) : "memory");
}
__device__ __forceinline__ void cp_commit() {
    asm volatile("cp.async.commit_group;" ::: "memory");
}
template <int N>
__device__ __forceinline__ void cp_wait() {
    asm volatile("cp.async.wait_group %0;" :: "n"(N) : "memory");
}

__device__ __forceinline__ void ldsm4(uint32_t* r, uint32_t addr) {
    asm volatile("ldmatrix.sync.aligned.m8n8.x4.shared.b16 {%0,%1,%2,%3}, [%4];"
                 : "=r"(r[0]), "=r"(r[1]), "=r"(r[2]), "=r"(r[3]) : "r"(addr));
}

__device__ __forceinline__ void mma_bf16(float* d, const uint32_t* a,
                                         uint32_t b0, uint32_t b1) {
    asm volatile(
        "mma.sync.aligned.m16n8k16.row.col.f32.bf16.bf16.f32 "
        "{%0,%1,%2,%3}, {%4,%5,%6,%7}, {%8,%9}, {%0,%1,%2,%3};"
        : "+f"(d[0]), "+f"(d[1]), "+f"(d[2]), "+f"(d[3])
        : "r"(a[0]), "r"(a[1]), "r"(a[2]), "r"(a[3]), "r"(b0), "r"(b1));
}

__device__ __forceinline__ uint32_t pack_bf(bf16 a, bf16 b) {
    return (uint32_t)__bfloat16_as_ushort(a) |
           ((uint32_t)__bfloat16_as_ushort(b) << 16);
}

// ---------------------------------------------------------------------------
// GEMM config: 128x128 tile, BLK_K=32, 8 warps (warp tile 32x64), 2 stages
// ---------------------------------------------------------------------------
constexpr int SKP     = 40;                  // smem tile col stride (bf16)
constexpr int TILE_B  = 128 * SKP * 2;       // 10240 bytes
constexpr int STAGE_B = 4 * TILE_B;          // Ah Al Wh Wl
constexpr int GEMM_SMEM = 2 * STAGE_B;       // 81920 bytes

__device__ __forceinline__ void gemm_issue(
    const bf16* __restrict__ base, int lw, uint32_t sdst0, int kc)
{
    const bf16* g0 = base + kc * 32;
#pragma unroll
    for (int i = 0; i < 8; i++) {
        const int chunk = i * 64 + lw;
        const int row = chunk >> 2, cs = chunk & 3;
        cp16(sdst0 + row * (SKP * 2) + cs * 16,
             g0 + (long long)row * Hd + cs * 8);
    }
}

// MODE 0: fp32 out (+bias). MODE 1: bf16 hi/lo out (+bias if non-null).
// MODE 2: bf16 hi/lo out + transposed hi/lo out (no bias).
template <int MODE>
__device__ void gemm_core(
    const bf16* __restrict__ Ah, const bf16* __restrict__ Al,
    const bf16* __restrict__ Wh, const bf16* __restrict__ Wl,
    const float* __restrict__ bias,
    float* __restrict__ C,
    bf16* __restrict__ Ch, bf16* __restrict__ Cl,
    bf16* __restrict__ Th, bf16* __restrict__ Tl,
    int m0, int n0)
{
    extern __shared__ char dsm[];
    const int tid = threadIdx.x;
    const int wid = tid >> 5, lane = tid & 31;
    const int m_off = (wid & 3) * 32;
    const int n_off = (wid >> 2) * 64;
    const uint32_t sbase = smem_u32(dsm);

    // per-thread cp.async tile assignment
    const int ltile = tid >> 6;
    const int lw = tid & 63;
    const bf16* gbase =
        (ltile == 0) ? Ah + (long long)m0 * Hd :
        (ltile == 1) ? Al + (long long)m0 * Hd :
        (ltile == 2) ? Wh + (long long)n0 * Hd :
                       Wl + (long long)n0 * Hd;
    const uint32_t sdst_tile = ltile * TILE_B;

    gemm_issue(gbase, lw, sbase + sdst_tile, 0);             cp_commit();
    gemm_issue(gbase, lw, sbase + STAGE_B + sdst_tile, 1);   cp_commit();

    float acc[2][8][4];
#pragma unroll
    for (int mi = 0; mi < 2; mi++)
#pragma unroll
        for (int j = 0; j < 8; j++)
#pragma unroll
            for (int e = 0; e < 4; e++) acc[mi][j][e] = 0.f;

    const int r_off = ((lane >> 3) & 1) * 8 + (lane & 7);
    const int c_off = (lane >> 4) * 8;

    for (int kc = 0; kc < 24; kc++) {
        cp_wait<1>();
        __syncthreads();
        const uint32_t sb = sbase + (kc & 1) * STAGE_B;
        const uint32_t aAh = sb + (m_off + r_off) * (SKP * 2) + c_off * 2;
        const uint32_t aAl = aAh + TILE_B;
        const uint32_t aWh = sb + 2 * TILE_B + (n_off + r_off) * (SKP * 2) + c_off * 2;
        const uint32_t aWl = aWh + TILE_B;

#pragma unroll
        for (int kk = 0; kk < 2; kk++) {
            uint32_t ah[2][4], alr[2][4];
#pragma unroll
            for (int t = 0; t < 2; t++) {
                ldsm4(ah[t],  aAh + t * 16 * (SKP * 2) + kk * 32);
                ldsm4(alr[t], aAl + t * 16 * (SKP * 2) + kk * 32);
            }
#pragma unroll
            for (int u = 0; u < 4; u++) {
                uint32_t bh[4];
                ldsm4(bh, aWh + u * 16 * (SKP * 2) + kk * 32);
#pragma unroll
                for (int mi = 0; mi < 2; mi++) {
                    mma_bf16(acc[mi][2 * u],     ah[mi],  bh[0], bh[2]);
                    mma_bf16(acc[mi][2 * u + 1], ah[mi],  bh[1], bh[3]);
                    mma_bf16(acc[mi][2 * u],     alr[mi], bh[0], bh[2]);
                    mma_bf16(acc[mi][2 * u + 1], alr[mi], bh[1], bh[3]);
                }
                uint32_t bl[4];
                ldsm4(bl, aWl + u * 16 * (SKP * 2) + kk * 32);
#pragma unroll
                for (int mi = 0; mi < 2; mi++) {
                    mma_bf16(acc[mi][2 * u],     ah[mi], bl[0], bl[2]);
                    mma_bf16(acc[mi][2 * u + 1], ah[mi], bl[1], bl[3]);
                }
            }
        }
        __syncthreads();
        if (kc + 2 < 24)
            gemm_issue(gbase, lw, sbase + (kc & 1) * STAGE_B + sdst_tile, kc + 2);
        cp_commit();
    }

    // stage accumulators through SMEM (f32 [128][132])
    float* sf = (float*)dsm;
    const int g = lane >> 2, t2 = (lane & 3) * 2;
#pragma unroll
    for (int mi = 0; mi < 2; mi++)
#pragma unroll
        for (int j = 0; j < 8; j++) {
            const int r = m_off + mi * 16 + g;
            const int c = n_off + j * 8 + t2;
            sf[r * 132 + c]           = acc[mi][j][0];
            sf[r * 132 + c + 1]       = acc[mi][j][1];
            sf[(r + 8) * 132 + c]     = acc[mi][j][2];
            sf[(r + 8) * 132 + c + 1] = acc[mi][j][3];
        }
    __syncthreads();

    if (MODE == 0) {
#pragma unroll 4
        for (int i = 0; i < 16; i++) {
            const int task = i * 256 + tid;
            const int row = task >> 5, c4 = (task & 31) * 4;
            float4 v = *(float4*)&sf[row * 132 + c4];
            v.x += bias[n0 + c4 + 0];
            v.y += bias[n0 + c4 + 1];
            v.z += bias[n0 + c4 + 2];
            v.w += bias[n0 + c4 + 3];
            *(float4*)(C + (long long)(m0 + row) * Hd + n0 + c4) = v;
        }
    } else {
#pragma unroll 4
        for (int i = 0; i < 16; i++) {
            const int task = i * 256 + tid;
            const int row = task >> 5, c4 = (task & 31) * 4;
            float4 v = *(float4*)&sf[row * 132 + c4];
            if (MODE == 1 && bias) {
                v.x += bias[n0 + c4 + 0];
                v.y += bias[n0 + c4 + 1];
                v.z += bias[n0 + c4 + 2];
                v.w += bias[n0 + c4 + 3];
            }
            bf16 h0 = __float2bfloat16(v.x), h1 = __float2bfloat16(v.y);
            bf16 h2 = __float2bfloat16(v.z), h3 = __float2bfloat16(v.w);
            bf16 l0 = __float2bfloat16(v.x - __bfloat162float(h0));
            bf16 l1 = __float2bfloat16(v.y - __bfloat162float(h1));
            bf16 l2 = __float2bfloat16(v.z - __bfloat162float(h2));
            bf16 l3 = __float2bfloat16(v.w - __bfloat162float(h3));
            const long long off = (long long)(m0 + row) * Hd + n0 + c4;
            *(uint2*)(Ch + off) = make_uint2(pack_bf(h0, h1), pack_bf(h2, h3));
            *(uint2*)(Cl + off) = make_uint2(pack_bf(l0, l1), pack_bf(l2, l3));
        }
        if (MODE == 2) {
            const int c = tid & 127;
            const int half = tid >> 7;
#pragma unroll 4
            for (int i = 0; i < 16; i++) {
                const int r4 = half * 64 + i * 4;
                float v0 = sf[(r4 + 0) * 132 + c];
                float v1 = sf[(r4 + 1) * 132 + c];
                float v2 = sf[(r4 + 2) * 132 + c];
                float v3 = sf[(r4 + 3) * 132 + c];
                bf16 h0 = __float2bfloat16(v0), h1 = __float2bfloat16(v1);
                bf16 h2 = __float2bfloat16(v2), h3 = __float2bfloat16(v3);
                bf16 l0 = __float2bfloat16(v0 - __bfloat162float(h0));
                bf16 l1 = __float2bfloat16(v1 - __bfloat162float(h1));
                bf16 l2 = __float2bfloat16(v2 - __bfloat162float(h2));
                bf16 l3 = __float2bfloat16(v3 - __bfloat162float(h3));
                const long long off = (long long)(n0 + c) * Hd + m0 + r4;
                *(uint2*)(Th + off) = make_uint2(pack_bf(h0, h1), pack_bf(h2, h3));
                *(uint2*)(Tl + off) = make_uint2(pack_bf(l0, l1), pack_bf(l2, l3));
            }
        }
    }
}

// ---------------------------------------------------------------------------
// GEMM wrappers
// ---------------------------------------------------------------------------
template <int MODE, int WSEL>
__global__ __launch_bounds__(256) void tc_gemm(
    const bf16* __restrict__ Ah, const bf16* __restrict__ Al, long long sAz,
    const bf16* __restrict__ Wh, const bf16* __restrict__ Wl,
    const float* __restrict__ bias, const int* __restrict__ lang,
    float* __restrict__ C, bf16* __restrict__ Ch, bf16* __restrict__ Cl,
    long long sCz)
{
    const int z = blockIdx.z;
    const bf16* wh = Wh;
    const bf16* wl = Wl;
    const float* bs = bias;
    if (WSEL) {
        const int lg = __ldg(&lang[z]);
        wh += (long long)lg * HH;
        wl += (long long)lg * HH;
        if (bias) bs += lg * Hd;
    }
    const long long ao = (long long)z * sAz;
    const long long co = (long long)z * sCz;
    gemm_core<MODE>(Ah + ao, Al + ao, wh, wl, bs,
                    (MODE == 0) ? C + co : nullptr,
                    (MODE != 0) ? Ch + co : nullptr,
                    (MODE != 0) ? Cl + co : nullptr,
                    nullptr, nullptr,
                    blockIdx.y * 128, blockIdx.x * 128);
}

// chain level: dst[z] = src[2p] @ src[2p+1], identity shortcuts, bf16 hi/lo
// in normal + transposed forms.
__global__ __launch_bounds__(256) void tc_chain(
    const bf16* __restrict__ sN_h, const bf16* __restrict__ sN_l,
    const bf16* __restrict__ sT_h, const bf16* __restrict__ sT_l,
    const unsigned char* __restrict__ fs,
    bf16* __restrict__ dN_h, bf16* __restrict__ dN_l,
    bf16* __restrict__ dT_h, bf16* __restrict__ dT_l,
    int spa, int dpa)
{
    const int z = blockIdx.z;
    const int a = z / dpa, p = z - a * dpa;
    const int li = a * spa + 2 * p;
    const unsigned char f1 = fs[li], f2 = fs[li + 1];
    const long long zo = (long long)z * HH;
    const int m0 = blockIdx.y * 128, n0 = blockIdx.x * 128;
    const int tid = threadIdx.x;

    if (f1 & f2) {   // identity
#pragma unroll 4
        for (int i = 0; i < 16; i++) {
            const int task = i * 256 + tid;
            const int row = task >> 5, c4 = (task & 31) * 4;
            const int gr = m0 + row, gc = n0 + c4;
            bf16 one = __float2bfloat16(1.f), zero = __float2bfloat16(0.f);
            bf16 h0 = (gc + 0 == gr) ? one : zero;
            bf16 h1 = (gc + 1 == gr) ? one : zero;
            bf16 h2 = (gc + 2 == gr) ? one : zero;
            bf16 h3 = (gc + 3 == gr) ? one : zero;
            const long long off = zo + (long long)gr * Hd + gc;
            uint2 hv = make_uint2(pack_bf(h0, h1), pack_bf(h2, h3));
            uint2 lv = make_uint2(0u, 0u);
            *(uint2*)(dN_h + off) = hv; *(uint2*)(dN_l + off) = lv;
            *(uint2*)(dT_h + off) = hv; *(uint2*)(dT_l + off) = lv;
        }
        return;
    }
    if (f1 | f2) {   // copy the non-identity factor (all 4 forms)
        const long long so = (long long)(f1 ? li + 1 : li) * HH;
#pragma unroll 4
        for (int i = 0; i < 8; i++) {
            const int idx = i * 256 + tid;
            const int row = idx >> 4, c8 = (idx & 15) * 8;
            const long long doff = zo + (long long)(m0 + row) * Hd + n0 + c8;
            const long long soff = so + (long long)(m0 + row) * Hd + n0 + c8;
            *(uint4*)(dN_h + doff) = *(const uint4*)(sN_h + soff);
            *(uint4*)(dN_l + doff) = *(const uint4*)(sN_l + soff);
            *(uint4*)(dT_h + doff) = *(const uint4*)(sT_h + soff);
            *(uint4*)(dT_l + doff) = *(const uint4*)(sT_l + soff);
        }
        return;
    }
    // real product: C = L @ R  ->  NT with W = R^T (row-major [n][k])
    gemm_core<2>(sN_h + (long long)li * HH, sN_l + (long long)li * HH,
                 sT_h + (long long)(li + 1) * HH, sT_l + (long long)(li + 1) * HH,
                 nullptr, nullptr,
                 dN_h + zo, dN_l + zo, dT_h + zo, dT_l + zo, m0, n0);
}

// ---------------------------------------------------------------------------
// fp32 -> bf16 hi/lo conversion
// ---------------------------------------------------------------------------
__global__ __launch_bounds__(256) void k_conv(
    const float* __restrict__ src, bf16* __restrict__ dh,
    bf16* __restrict__ dl)
{
    const long long i4 = ((long long)blockIdx.x * 256 + threadIdx.x) * 4;
    float4 v = *(const float4*)(src + i4);
    bf16 h0 = __float2bfloat16(v.x), h1 = __float2bfloat16(v.y);
    bf16 h2 = __float2bfloat16(v.z), h3 = __float2bfloat16(v.w);
    bf16 l0 = __float2bfloat16(v.x - __bfloat162float(h0));
    bf16 l1 = __float2bfloat16(v.y - __bfloat162float(h1));
    bf16 l2 = __float2bfloat16(v.z - __bfloat162float(h2));
    bf16 l3 = __float2bfloat16(v.w - __bfloat162float(h3));
    *(uint2*)(dh + i4) = make_uint2(pack_bf(h0, h1), pack_bf(h2, h3));
    *(uint2*)(dl + i4) = make_uint2(pack_bf(l0, l1), pack_bf(l2, l3));
}

// ---------------------------------------------------------------------------
// Chain flags + leaf factors
// ---------------------------------------------------------------------------
__global__ void k_flags(const int* __restrict__ lang,
                        unsigned char* fF, unsigned char* fP1, unsigned char* fP2)
{
    if (threadIdx.x == 0 && blockIdx.x == 0) {
        for (int a = 0; a < NL; a++) {
            for (int j = 0; j < 8; j++) fF[a * 8 + j] = (lang[j] == a) ? 1 : 0;
            for (int p = 0; p < 4; p++)
                fP1[a * 4 + p] = fF[a * 8 + 2 * p] & fF[a * 8 + 2 * p + 1];
            for (int p = 0; p < 2; p++)
                fP2[a * 2 + p] = fP1[a * 4 + 2 * p] & fP1[a * 4 + 2 * p + 1];
        }
    }
}

__device__ __forceinline__ void split_store4(
    bf16* dh, bf16* dl, long long off, float x, float y, float z, float w)
{
    bf16 h0 = __float2bfloat16(x), h1 = __float2bfloat16(y);
    bf16 h2 = __float2bfloat16(z), h3 = __float2bfloat16(w);
    bf16 l0 = __float2bfloat16(x - __bfloat162float(h0));
    bf16 l1 = __float2bfloat16(y - __bfloat162float(h1));
    bf16 l2 = __float2bfloat16(z - __bfloat162float(h2));
    bf16 l3 = __float2bfloat16(w - __bfloat162float(h3));
    *(uint2*)(dh + off) = make_uint2(pack_bf(h0, h1), pack_bf(h2, h3));
    *(uint2*)(dl + off) = make_uint2(pack_bf(l0, l1), pack_bf(l2, l3));
}

__global__ __launch_bounds__(256) void k_factors(
    const float* __restrict__ alignT, const int* __restrict__ lang,
    bf16* __restrict__ Fh, bf16* __restrict__ Fl,
    bf16* __restrict__ FTh, bf16* __restrict__ FTl)
{
    const int node = blockIdx.y;
    const int a = node >> 3, j = node & 7;
    const int c = __ldg(&lang[j]);
    const long long nb = (long long)node * HH;
    const long long i4 = ((long long)blockIdx.x * 256 + threadIdx.x) * 4;
    const int r = (int)(i4 / Hd), col = (int)(i4 % Hd);

    if (c == a) {
        float v0 = (col + 0 == r) ? 1.f : 0.f;
        float v1 = (col + 1 == r) ? 1.f : 0.f;
        float v2 = (col + 2 == r) ? 1.f : 0.f;
        float v3 = (col + 3 == r) ? 1.f : 0.f;
        split_store4(Fh,  Fl,  nb + i4, v0, v1, v2, v3);
        split_store4(FTh, FTl, nb + i4, v0, v1, v2, v3);
    } else {
        const float* sm = alignT + (long long)(a * NL + c) * HH;
        float4 v = *(const float4*)(sm + i4);
        split_store4(Fh, Fl, nb + i4, v.x, v.y, v.z, v.w);
        float t0 = sm[(long long)(col + 0) * Hd + r];
        float t1 = sm[(long long)(col + 1) * Hd + r];
        float t2 = sm[(long long)(col + 2) * Hd + r];
        float t3 = sm[(long long)(col + 3) * Hd + r];
        split_store4(FTh, FTl, nb + i4, t0, t1, t2, t3);
    }
}

// ---------------------------------------------------------------------------
// Flash attention (fp32 SIMT, unchanged from round 1 — passed)
// ---------------------------------------------------------------------------
__global__ __launch_bounds__(256) void k_attn(
    const float* __restrict__ Q, const float* __restrict__ K,
    const float* __restrict__ V, float* __restrict__ O)
{
    __shared__ float Qs[64 * 64];
    __shared__ float KP[64 * 64];
    __shared__ float Vs[64 * 64];

    const int qt = blockIdx.x, h = blockIdx.y, b = blockIdx.z;
    const int tid = threadIdx.x;
    const int ty = tid >> 4, tx = tid & 15;
    const long long qbase = ((long long)(b * S + qt * 64)) * Hd + h * 64;

#pragma unroll
    for (int u = 0; u < 4; u++) {
        const int fidx = u * 256 + tid;
        const int r = fidx >> 4;
        const int d = (fidx & 15) * 4;
        float4 v = *(const float4*)(Q + qbase + (long long)r * Hd + d);
        v.x *= 0.125f; v.y *= 0.125f; v.z *= 0.125f; v.w *= 0.125f;
        *(float4*)&Qs[r * 64 + d] = v;
    }

    float m[4], l[4], o[4][4];
#pragma unroll
    for (int i = 0; i < 4; i++) {
        m[i] = -1e30f; l[i] = 0.f;
#pragma unroll
        for (int j = 0; j < 4; j++) o[i][j] = 0.f;
    }

    for (int kt = 0; kt < S / 64; kt++) {
        const long long kbase = ((long long)(b * S + kt * 64)) * Hd + h * 64;
        __syncthreads();
#pragma unroll
        for (int u = 0; u < 4; u++) {
            const int fidx = u * 256 + tid;
            const int r = fidx >> 4;
            const int d = (fidx & 15) * 4;
            float4 kv = *(const float4*)(K + kbase + (long long)r * Hd + d);
            KP[(d + 0) * 64 + r] = kv.x;
            KP[(d + 1) * 64 + r] = kv.y;
            KP[(d + 2) * 64 + r] = kv.z;
            KP[(d + 3) * 64 + r] = kv.w;
            *(float4*)&Vs[r * 64 + d] =
                *(const float4*)(V + kbase + (long long)r * Hd + d);
        }
        __syncthreads();

        float s[4][4];
#pragma unroll
        for (int i = 0; i < 4; i++)
#pragma unroll
            for (int j = 0; j < 4; j++) s[i][j] = 0.f;

#pragma unroll
        for (int d0 = 0; d0 < 64; d0 += 4) {
            float a0[4], a1[4], a2[4], a3[4];
            *(float4*)a0 = *(const float4*)&Qs[(ty * 4 + 0) * 64 + d0];
            *(float4*)a1 = *(const float4*)&Qs[(ty * 4 + 1) * 64 + d0];
            *(float4*)a2 = *(const float4*)&Qs[(ty * 4 + 2) * 64 + d0];
            *(float4*)a3 = *(const float4*)&Qs[(ty * 4 + 3) * 64 + d0];
#pragma unroll
            for (int dd = 0; dd < 4; dd++) {
                const float b0 = KP[(d0 + dd) * 64 + tx];
                const float b1 = KP[(d0 + dd) * 64 + tx + 16];
                const float b2 = KP[(d0 + dd) * 64 + tx + 32];
                const float b3 = KP[(d0 + dd) * 64 + tx + 48];
                s[0][0] += a0[dd] * b0; s[0][1] += a0[dd] * b1;
                s[0][2] += a0[dd] * b2; s[0][3] += a0[dd] * b3;
                s[1][0] += a1[dd] * b0; s[1][1] += a1[dd] * b1;
                s[1][2] += a1[dd] * b2; s[1][3] += a1[dd] * b3;
                s[2][0] += a2[dd] * b0; s[2][1] += a2[dd] * b1;
                s[2][2] += a2[dd] * b2; s[2][3] += a2[dd] * b3;
                s[3][0] += a3[dd] * b0; s[3][1] += a3[dd] * b1;
                s[3][2] += a3[dd] * b2; s[3][3] += a3[dd] * b3;
            }
        }

        float p[4][4];
#pragma unroll
        for (int i = 0; i < 4; i++) {
            float mx = fmaxf(fmaxf(s[i][0], s[i][1]), fmaxf(s[i][2], s[i][3]));
#pragma unroll
            for (int off = 8; off >= 1; off >>= 1)
                mx = fmaxf(mx, __shfl_xor_sync(0xffffffffu, mx, off));
            const float mn = fmaxf(m[i], mx);
            const float alpha = __expf(m[i] - mn);
            m[i] = mn;
            float rs = 0.f;
#pragma unroll
            for (int j = 0; j < 4; j++) {
                p[i][j] = __expf(s[i][j] - mn);
                rs += p[i][j];
            }
#pragma unroll
            for (int off = 8; off >= 1; off >>= 1)
                rs += __shfl_xor_sync(0xffffffffu, rs, off);
            l[i] = l[i] * alpha + rs;
            o[i][0] *= alpha; o[i][1] *= alpha;
            o[i][2] *= alpha; o[i][3] *= alpha;
        }

        __syncthreads();
#pragma unroll
        for (int i = 0; i < 4; i++)
#pragma unroll
            for (int j = 0; j < 4; j++)
                KP[(ty * 4 + i) * 64 + tx + 16 * j] = p[i][j];
        __syncthreads();

#pragma unroll
        for (int k = 0; k < 64; k++) {
            const float4 v = *(const float4*)&Vs[k * 64 + tx * 4];
            const float p0 = KP[(ty * 4 + 0) * 64 + k];
            const float p1 = KP[(ty * 4 + 1) * 64 + k];
            const float p2 = KP[(ty * 4 + 2) * 64 + k];
            const float p3 = KP[(ty * 4 + 3) * 64 + k];
            o[0][0] += p0 * v.x; o[0][1] += p0 * v.y; o[0][2] += p0 * v.z; o[0][3] += p0 * v.w;
            o[1][0] += p1 * v.x; o[1][1] += p1 * v.y; o[1][2] += p1 * v.z; o[1][3] += p1 * v.w;
            o[2][0] += p2 * v.x; o[2][1] += p2 * v.y; o[2][2] += p2 * v.z; o[2][3] += p2 * v.w;
            o[3][0] += p3 * v.x; o[3][1] += p3 * v.y; o[3][2] += p3 * v.z; o[3][3] += p3 * v.w;
        }
    }

#pragma unroll
    for (int i = 0; i < 4; i++) {
        const float inv = 1.f / l[i];
        float4 v = make_float4(o[i][0] * inv, o[i][1] * inv,
                               o[i][2] * inv, o[i][3] * inv);
        *(float4*)(O + qbase + (long long)(ty * 4 + i) * Hd + tx * 4) = v;
    }
}

// ---------------------------------------------------------------------------
// Residual + LayerNorm
// ---------------------------------------------------------------------------
__global__ __launch_bounds__(256) void k_ln(
    const float* __restrict__ X, const float* __restrict__ Rres,
    const float* __restrict__ gam, const float* __restrict__ bet,
    float* __restrict__ out)
{
    const int row = blockIdx.x;
    const long long base = (long long)row * Hd;
    const int tid = threadIdx.x;

    float v[3];
    float s = 0.f, s2 = 0.f;
#pragma unroll
    for (int u = 0; u < 3; u++) {
        const int idx = tid + u * 256;
        const float val = X[base + idx] + Rres[base + idx];
        v[u] = val; s += val; s2 += val * val;
    }
#pragma unroll
    for (int off = 16; off >= 1; off >>= 1) {
        s  += __shfl_xor_sync(0xffffffffu, s, off);
        s2 += __shfl_xor_sync(0xffffffffu, s2, off);
    }
    __shared__ float ss[8], ss2[8], mv[2];
    const int wid = tid >> 5, lane = tid & 31;
    if (lane == 0) { ss[wid] = s; ss2[wid] = s2; }
    __syncthreads();
    if (tid == 0) {
        float S_ = 0.f, S2_ = 0.f;
        for (int w = 0; w < 8; w++) { S_ += ss[w]; S2_ += ss2[w]; }
        const float mean = S_ * (1.f / 768.f);
        const float var  = S2_ * (1.f / 768.f) - mean * mean;
        mv[0] = mean;
        mv[1] = rsqrtf(var + 1e-5f);
    }
    __syncthreads();
    const float mean = mv[0], rstd = mv[1];
#pragma unroll
    for (int u = 0; u < 3; u++) {
        const int idx = tid + u * 256;
        out[base + idx] = (v[u] - mean) * rstd * gam[idx] + bet[idx];
    }
}

// ---------------------------------------------------------------------------
// kernel_launch
// ---------------------------------------------------------------------------
#define SYM(v, s) cudaGetSymbolAddress((void**)&v, s)

extern "C" void kernel_launch(void* const* d_in, const int* in_sizes, int n_in,
                              void* d_out, int out_size)
{
    const float* hs      = (const float*)d_in[0];
    const int*   lang    = (const int*)  d_in[1];
    const float* Wq_lang = (const float*)d_in[3];
    const float* bq_lang = (const float*)d_in[4];
    const float* Wk_lang = (const float*)d_in[5];
    const float* bk_lang = (const float*)d_in[6];
    const float* in_w    = (const float*)d_in[7];
    const float* in_b    = (const float*)d_in[8];
    const float* out_w   = (const float*)d_in[9];
    const float* out_b   = (const float*)d_in[10];
    const float* alignT  = (const float*)d_in[11];
    const float* proj_w  = (const float*)d_in[12];
    const float* proj_b  = (const float*)d_in[13];
    const float* ln_g    = (const float*)d_in[14];
    const float* ln_b    = (const float*)d_in[15];
    float* out = (float*)d_out;

    float *Qp, *Kp, *Vp, *ctx, *obuf;
    SYM(Qp, g_Q); SYM(Kp, g_K); SYM(Vp, g_V); SYM(ctx, g_ctx); SYM(obuf, g_o);

    bf16 *hs_h, *hs_l, *q_h, *q_l, *k_h, *k_l, *ctx_h, *ctx_l;
    bf16 *al_h, *al_l, *al2_h, *al2_l;
    SYM(hs_h, g_hs_h);   SYM(hs_l, g_hs_l);
    SYM(q_h, g_q_h);     SYM(q_l, g_q_l);
    SYM(k_h, g_k_h);     SYM(k_l, g_k_l);
    SYM(ctx_h, g_ctx_h); SYM(ctx_l, g_ctx_l);
    SYM(al_h, g_al_h);   SYM(al_l, g_al_l);
    SYM(al2_h, g_al2_h); SYM(al2_l, g_al2_l);

    bf16 *Wq_h, *Wq_l, *Wk_h, *Wk_l, *inw_h, *inw_l, *ow_h, *ow_l, *pw_h, *pw_l;
    SYM(Wq_h, g_Wq_h);   SYM(Wq_l, g_Wq_l);
    SYM(Wk_h, g_Wk_h);   SYM(Wk_l, g_Wk_l);
    SYM(inw_h, g_inw_h); SYM(inw_l, g_inw_l);
    SYM(ow_h, g_ow_h);   SYM(ow_l, g_ow_l);
    SYM(pw_h, g_pw_h);   SYM(pw_l, g_pw_l);

    bf16 *F_h, *F_l, *FT_h, *FT_l, *P1_h, *P1_l, *QT1_h, *QT1_l;
    bf16 *P2_h, *P2_l, *QT2_h, *QT2_l, *M_h, *M_l, *MT_h, *MT_l;
    SYM(F_h, g_F_h);   SYM(F_l, g_F_l);   SYM(FT_h, g_FT_h); SYM(FT_l, g_FT_l);
    SYM(P1_h, g_P1_h); SYM(P1_l, g_P1_l); SYM(QT1_h, g_QT1_h); SYM(QT1_l, g_QT1_l);
    SYM(P2_h, g_P2_h); SYM(P2_l, g_P2_l); SYM(QT2_h, g_QT2_h); SYM(QT2_l, g_QT2_l);
    SYM(M_h, g_M_h);   SYM(M_l, g_M_l);   SYM(MT_h, g_MT_h); SYM(MT_l, g_MT_l);

    unsigned char *fF, *fP1, *fP2;
    SYM(fF, g_fF); SYM(fP1, g_fP1); SYM(fP2, g_fP2);

    cudaFuncSetAttribute(tc_gemm<0, 0>, cudaFuncAttributeMaxDynamicSharedMemorySize, GEMM_SMEM);
    cudaFuncSetAttribute(tc_gemm<1, 0>, cudaFuncAttributeMaxDynamicSharedMemorySize, GEMM_SMEM);
    cudaFuncSetAttribute(tc_gemm<1, 1>, cudaFuncAttributeMaxDynamicSharedMemorySize, GEMM_SMEM);
    cudaFuncSetAttribute(tc_chain,      cudaFuncAttributeMaxDynamicSharedMemorySize, GEMM_SMEM);

    const long long sBH = (long long)S * Hd;
    const dim3 thr(256);

    // --- conversions (weights + hs) ---
    k_conv<<<BS * Hd / 1024, thr>>>(hs, hs_h, hs_l);
    k_conv<<<(int)(NL * HH / 1024), thr>>>(Wq_lang, Wq_h, Wq_l);
    k_conv<<<(int)(NL * HH / 1024), thr>>>(Wk_lang, Wk_h, Wk_l);
    k_conv<<<(int)(3 * HH / 1024), thr>>>(in_w, inw_h, inw_l);
    k_conv<<<(int)(HH / 1024), thr>>>(out_w, ow_h, ow_l);
    k_conv<<<(int)(HH / 1024), thr>>>(proj_w, pw_h, pw_l);

    // --- chain ---
    k_flags<<<1, 32>>>(lang, fF, fP1, fP2);
    k_factors<<<dim3((int)(HH / 1024), NL * 8), thr>>>(alignT, lang, F_h, F_l, FT_h, FT_l);
    tc_chain<<<dim3(6, 6, NL * 4), thr, GEMM_SMEM>>>(F_h, F_l, FT_h, FT_l, fF,
                                                     P1_h, P1_l, QT1_h, QT1_l, 8, 4);
    tc_chain<<<dim3(6, 6, NL * 2), thr, GEMM_SMEM>>>(P1_h, P1_l, QT1_h, QT1_l, fP1,
                                                     P2_h, P2_l, QT2_h, QT2_l, 4, 2);
    tc_chain<<<dim3(6, 6, NL), thr, GEMM_SMEM>>>(P2_h, P2_l, QT2_h, QT2_l, fP2,
                                                 M_h, M_l, MT_h, MT_l, 2, 1);

    // --- per-language q/k projections (bf16 out) ---
    tc_gemm<1, 1><<<dim3(6, 6, Bsz), thr, GEMM_SMEM>>>(
        hs_h, hs_l, sBH, Wq_h, Wq_l, bq_lang, lang, nullptr, q_h, q_l, sBH);
    tc_gemm<1, 1><<<dim3(6, 6, Bsz), thr, GEMM_SMEM>>>(
        hs_h, hs_l, sBH, Wk_h, Wk_l, bk_lang, lang, nullptr, k_h, k_l, sBH);

    // --- QKV (fp32 out) ---
    tc_gemm<0, 0><<<dim3(6, 48, 1), thr, GEMM_SMEM>>>(
        q_h, q_l, 0, inw_h, inw_l, in_b, nullptr, Qp, nullptr, nullptr, 0);
    tc_gemm<0, 0><<<dim3(6, 48, 1), thr, GEMM_SMEM>>>(
        k_h, k_l, 0, inw_h + HH, inw_l + HH, in_b + Hd, nullptr, Kp, nullptr, nullptr, 0);
    tc_gemm<0, 0><<<dim3(6, 48, 1), thr, GEMM_SMEM>>>(
        hs_h, hs_l, 0, inw_h + 2 * HH, inw_l + 2 * HH, in_b + 2 * Hd, nullptr,
        Vp, nullptr, nullptr, 0);

    // --- attention ---
    k_attn<<<dim3(S / 64, NH, Bsz), thr>>>(Qp, Kp, Vp, ctx);
    k_conv<<<BS * Hd / 1024, thr>>>(ctx, ctx_h, ctx_l);

    // --- out_proj (bf16 out) ---
    tc_gemm<1, 0><<<dim3(6, 48, 1), thr, GEMM_SMEM>>>(
        ctx_h, ctx_l, 0, ow_h, ow_l, out_b, nullptr, nullptr, al_h, al_l, 0);

    // --- aligned @ M[lang[b]] (bf16 out, W = M^T selected per batch) ---
    tc_gemm<1, 1><<<dim3(6, 6, Bsz), thr, GEMM_SMEM>>>(
        al_h, al_l, sBH, MT_h, MT_l, nullptr, lang, nullptr, al2_h, al2_l, sBH);

    // --- final proj (fp32 out) ---
    tc_gemm<0, 0><<<dim3(6, 48, 1), thr, GEMM_SMEM>>>(
        al2_h, al2_l, 0, pw_h, pw_l, proj_b, nullptr, obuf, nullptr, nullptr, 0);

    // --- residual + LayerNorm ---
    k_ln<<<BS, thr>>>(obuf, hs, ln_g, ln_b, out);
}